// round 12
// baseline (speedup 1.0000x reference)
#include <cuda_runtime.h>

#define HH 256
#define WW 256
#define PP 512
// ALPHA = -5.0f, 1/ALPHA = -0.2f

typedef unsigned long long ull;

__device__ float g_sum[PP];          // zero-init at load; reset by epilogue
__device__ float g_numA[HH];
__device__ float g_denA[HH];
__device__ int   g_ctr = 0;

__device__ __forceinline__ float fsqrt_a(float x) {
    float r; asm("sqrt.approx.f32 %0, %1;" : "=f"(r) : "f"(x)); return r;
}
__device__ __forceinline__ float frcp_a(float x) {
    float r; asm("rcp.approx.f32 %0, %1;" : "=f"(r) : "f"(x)); return r;
}
__device__ __forceinline__ ull pk2(float lo, float hi) {
    ull r; asm("mov.b64 %0, {%1, %2};" : "=l"(r) : "f"(lo), "f"(hi)); return r;
}
__device__ __forceinline__ void upk2(ull v, float& lo, float& hi) {
    asm("mov.b64 {%0, %1}, %2;" : "=f"(lo), "=f"(hi) : "l"(v));
}
__device__ __forceinline__ ull f2add(ull a, ull b) {
    ull r; asm("add.rn.f32x2 %0, %1, %2;" : "=l"(r) : "l"(a), "l"(b)); return r;
}
__device__ __forceinline__ ull f2mul(ull a, ull b) {
    ull r; asm("mul.rn.f32x2 %0, %1, %2;" : "=l"(r) : "l"(a), "l"(b)); return r;
}
__device__ __forceinline__ ull f2fma(ull a, ull b, ull c) {
    ull r; asm("fma.rn.f32x2 %0, %1, %2, %3;" : "=l"(r) : "l"(a), "l"(b), "l"(c)); return r;
}

// Phase A: min squared distance over 256 points (128 quads), f32x2 packed.
__device__ __forceinline__ float phaseA_min(const float4* __restrict__ ptab,
                                            float xf) {
    ull XF2 = pk2(xf, xf);
    float mins = 3.4e38f;
#pragma unroll 8
    for (int k = 0; k < 128; ++k) {
        float4 q = ptab[k];              // (-px0,-px1,dxs0,dxs1): aligned pairs
        ull NPX = pk2(q.x, q.y);
        ull DXS = pk2(q.z, q.w);
        ull DY  = f2add(XF2, NPX);
        ull S   = f2fma(DY, DY, DXS);
        float s0, s1; upk2(S, s0, s1);
        mins = fminf(mins, fminf(s0, s1));
    }
    return mins;
}

// Phase B: soft-min power sum over 256 pixels for one point.
// EXACT dy recurrence (dy += 2 is exact in fp32) + scalar MUFU;
// packed math only for the ^5 polynomial accumulate.
__device__ __forceinline__ float phaseB_sum(const float4* __restrict__ hb,
                                            float np, float dxs) {
    float dyA = np;                      // dy at even pixel x=0 (np = -px)
    float dyB = np + 1.0f;               // dy at odd pixel x=1
    ull SACC  = 0;
#pragma unroll 8
    for (int k = 0; k < 128; ++k) {
        float4 q = hb[k];                // (h0,h1,bb0,bb1) one LDS.128
        float sA = fmaf(dyA, dyA, dxs);  // exact, always >= dxs > 0
        float sB = fmaf(dyB, dyB, dxs);
        float dA = fsqrt_a(sA);          // MUFU sqrt
        float dB = fsqrt_a(sB);
        float wA = fmaf(q.x, dA, q.z);   // w = h*d + (1-h)*M
        float wB = fmaf(q.y, dB, q.w);
        float qA = frcp_a(wA);           // MUFU rcp
        float qB = frcp_a(wB);
        ull Y  = pk2(qA, qB);
        ull Q2 = f2mul(Y, Y);
        ull Q4 = f2mul(Q2, Q2);
        SACC = f2fma(Q4, Y, SACC);       // += w^-5
        dyA += 2.0f;
        dyB += 2.0f;
    }
    float SA, SB; upk2(SACC, SA, SB);
    return SA + SB;
}

// ---------------------------------------------------------------------------
// 128 blocks x 1024 threads (one wave). Block b owns rows 2b, 2b+1.
// Even warps run A->B, odd warps B->A with no barrier between: fma-heavy A
// fills MUFU-stall cycles of B across warps. Last block finalizes + resets.
// ---------------------------------------------------------------------------
__global__ __launch_bounds__(1024, 1) void k_all(const float* __restrict__ hm,
                                                 const float* __restrict__ pts,
                                                 float* __restrict__ out) {
    __shared__ float4 pre4[2][PP / 2];   // per row: (-px0,-px1,dxs0,dxs1)
    __shared__ float  s_hm[2][WW];       // per row: raw h
    __shared__ float4 s_hb[2][WW / 2];   // per row: (h0,h1,bb0,bb1)
    __shared__ float  s_min[2][2][256];  // per row, per point-half: min dist2
    __shared__ float  s_red[32], s_red2[32];
    __shared__ float  s_M;

    int tid  = threadIdx.x;              // 0..1023
    int row  = tid >> 9;                 // 0/1 within the row pair
    int t    = tid & 511;                // point index within row
    int y    = blockIdx.x * 2 + row;

    // ---- per-row point table (quad layout) + corner max (separable) --------
    float py = pts[2 * t], px = pts[2 * t + 1];
    float dx = (float)y - py;
    {
        float* prefs = (float*)pre4[row];
        int cell = t >> 1, par = t & 1;
        prefs[cell * 4 + par]     = -px;
        prefs[cell * 4 + 2 + par] = dx * dx;
    }
    float my = fmaxf(py, 255.0f - py);
    float mx = fmaxf(px, 255.0f - px);
    float lmax = fmaf(my, my, mx * mx);

    float h = 0.f;
    if (t < WW) {
        h = hm[y * WW + t];
        s_hm[row][t] = h;
    }

    int warp = tid >> 5, lane = tid & 31;
    for (int o = 16; o > 0; o >>= 1)
        lmax = fmaxf(lmax, __shfl_down_sync(0xffffffffu, lmax, o));
    if (lane == 0) s_red[warp] = lmax;
    __syncthreads();
    if (tid == 0) {
        float m = s_red[0];
#pragma unroll
        for (int i = 1; i < 32; ++i) m = fmaxf(m, s_red[i]);
        s_M = sqrtf(m);
    }
    __syncthreads();
    float M = s_M;

    // ---- (h, bb) pixel-pair quads (t < 128 per row) -------------------------
    if (t < WW / 2) {
        float h0 = s_hm[row][2 * t], h1 = s_hm[row][2 * t + 1];
        s_hb[row][t] = make_float4(h0, h1, fmaf(-h0, M, M), fmaf(-h1, M, M));
    }
    __syncthreads();

    // ---------------- interleaved phases (no barrier between) ----------------
    int p  = tid & 255;                  // phase-A pixel
    int hp = (tid >> 8) & 1;             // phase-A point half
    const float4* ptabA = &pre4[row][hp * 128];
    const float*  prefs = (const float*)pre4[row];
    int base = (t >> 1) * 4 + (t & 1);
    float np  = prefs[base];             // -px for point t
    float dxs = prefs[base + 2];         // (y-py)^2
    const float4* hb = s_hb[row];

    if (warp & 1) {
        float sb = phaseB_sum(hb, np, dxs);
        atomicAdd(&g_sum[t], sb);
        s_min[row][hp][p] = phaseA_min(ptabA, (float)p);
    } else {
        s_min[row][hp][p] = phaseA_min(ptabA, (float)p);
        float sb = phaseB_sum(hb, np, dxs);
        atomicAdd(&g_sum[t], sb);
    }
    __syncthreads();

    // ---------------- term-1 reduction (needs all s_min) ---------------------
    {
        float t1 = 0.f, ah = 0.f;
        if (hp == 0) {                   // these threads hold h for pixel p
            float mins = fminf(s_min[row][0][p], s_min[row][1][p]);
            t1 = h * sqrtf(mins);
            ah = fabsf(h);
        }
        for (int o = 16; o > 0; o >>= 1) {
            t1 += __shfl_down_sync(0xffffffffu, t1, o);
            ah += __shfl_down_sync(0xffffffffu, ah, o);
        }
        if (lane == 0) { s_red[warp] = t1; s_red2[warp] = ah; }
    }
    __syncthreads();
    if (t == 0) {                        // one finisher per row
        int w0 = row * 16;               // row's hp==0 warps
        float a = 0.f, b = 0.f;
#pragma unroll
        for (int i = 0; i < 8; ++i) { a += s_red[w0 + i]; b += s_red2[w0 + i]; }
        g_numA[y] = a;
        g_denA[y] = b;
    }

    // ---------------- last-block epilogue ------------------------------------
    __shared__ int s_last;
    __threadfence();
    __syncthreads();
    if (tid == 0) s_last = (atomicAdd(&g_ctr, 1) == (int)gridDim.x - 1);
    __syncthreads();
    if (!s_last) return;

    float* red = (float*)pre4;           // reuse smem
    float* r2  = (float*)s_hm;
    float* r3  = (float*)s_min;
    if (tid < PP) {
        float Ssum = g_sum[tid];
        red[tid] = powf(Ssum * (1.0f / (HH * WW)), -0.2f);  // mean^(1/ALPHA)
        g_sum[tid] = 0.f;                // reset for next replay
    }
    if (tid < HH) { r2[tid] = g_numA[tid]; r3[tid] = g_denA[tid]; }
    __syncthreads();
    for (int o = 256; o > 0; o >>= 1) {
        if (tid < o) red[tid] += red[tid + o];
        __syncthreads();
    }
    for (int o = 128; o > 0; o >>= 1) {
        if (tid < o) { r2[tid] += r2[tid + o]; r3[tid] += r3[tid + o]; }
        __syncthreads();
    }
    if (tid == 0) {
        out[0] = r2[0] / r3[0] + red[0] * (1.0f / PP);
        g_ctr = 0;                       // reset for next replay
    }
}

extern "C" void kernel_launch(void* const* d_in, const int* in_sizes, int n_in,
                              void* d_out, int out_size) {
    (void)in_sizes; (void)n_in; (void)out_size;
    const float* hm  = (const float*)d_in[0];   // heat_map (256*256)
    const float* pts = (const float*)d_in[1];   // points   (512*2)
    float* out = (float*)d_out;

    k_all<<<HH / 2, 1024>>>(hm, pts, out);
}